// round 12
// baseline (speedup 1.0000x reference)
#include <cuda_runtime.h>
#include <cuda_fp16.h>
#include <cstdint>

#define MAXN 100000
#define EPB  256            // edges per block
#define NTHR 256

// ---------------- device scratch ----------------
__device__ __half d_g[(size_t)MAXN * 256];               // g[n][d][h] fp16, 51.2 MB
__device__ float d_denom[MAXN * 4];                      // per (node, head)
__device__ __align__(16) __half d_Bimg[2 * 128 * 72];    // [hi(128 cols) | lo(128 cols)][k pad 72]
__device__ int g_is64;

// ---------------- helpers ----------------
__device__ __forceinline__ void red4(float* p, float4 v) {
    asm volatile("red.global.add.v4.f32 [%0], {%1, %2, %3, %4};"
                 :: "l"(p), "f"(v.x), "f"(v.y), "f"(v.z), "f"(v.w) : "memory");
}
__device__ __forceinline__ long long load_idx(const void* p, long long i) {
    if (g_is64) return ((const long long*)p)[i];
    return (long long)((const int*)p)[i];
}
__device__ __forceinline__ uint32_t smem_u32(const void* p) {
    uint32_t a;
    asm("{ .reg .u64 t; cvta.to.shared.u64 t, %1; cvt.u32.u64 %0, t; }" : "=r"(a) : "l"(p));
    return a;
}
__device__ __forceinline__ uint32_t pack_h2(float a, float b) {
    __half2 h = __floats2half2_rn(a, b);
    return *(uint32_t*)&h;
}
__device__ __forceinline__ void mma16816(float c[4], const uint32_t a[4],
                                         uint32_t b0, uint32_t b1) {
    asm volatile("mma.sync.aligned.m16n8k16.row.col.f32.f16.f16.f32 "
                 "{%0,%1,%2,%3}, {%4,%5,%6,%7}, {%8,%9}, {%0,%1,%2,%3};"
                 : "+f"(c[0]), "+f"(c[1]), "+f"(c[2]), "+f"(c[3])
                 : "r"(a[0]), "r"(a[1]), "r"(a[2]), "r"(a[3]), "r"(b0), "r"(b1));
}
#define LDMX4(r, a)                                                        \
    asm volatile("ldmatrix.sync.aligned.m8n8.x4.shared.b16 {%0,%1,%2,%3}, [%4];" \
        : "=r"((r)[0]), "=r"((r)[1]), "=r"((r)[2]), "=r"((r)[3]) : "r"(a))

// ---------------- smem layout (bytes) ----------------
#define SM_SRC 0                       // int[256]            1024
#define SM_BE  1024                    // float[64]           256
#define SM_ATT 1280                    // float[256*4]        4096
#define SM_BHI 5376                    // half[128][72]       18432
#define SM_BLO 23808                   // half[128][72]       18432
#define SM_AHI 42240                   // half[256][72]       36864
#define SMEM_BYTES 79104

// ================= kernel 0: dtype detect =================
__global__ void detect_kernel(const int* __restrict__ p) {
    if (threadIdx.x == 0) {
        int any = 0;
        for (int i = 1; i < 256; i += 2) any |= p[i];
        g_is64 = (any == 0) ? 1 : 0;
    }
}

// ================= kernel 1: zero out + denom =================
__global__ void zero_kernel(float4* __restrict__ out, int Nn) {
    int i = blockIdx.x * blockDim.x + threadIdx.x;
    int st = gridDim.x * blockDim.x;
    float4 z = make_float4(0.f, 0.f, 0.f, 0.f);
    int n4 = Nn * 16;
    for (int j = i; j < n4; j += st) out[j] = z;
    float4* dn = (float4*)d_denom;
    for (int j = i; j < Nn; j += st) dn[j] = z;
}

// ================= kernel 2: per-node g = Wk^T (x @ Wq)  (+ block 0 builds B image) =================
__global__ void __launch_bounds__(256) prep_kernel(const float* __restrict__ x,
                                                   const float* __restrict__ Wq,
                                                   const float* __restrict__ Wv,
                                                   const float* __restrict__ We,
                                                   const float* __restrict__ Wk,
                                                   int Nn) {
    // block 0: fp16 hi/lo split B image, cols 0..63 Wv, 64..127 We
    if (blockIdx.x == 0 && threadIdx.x < 128) {
        int n = threadIdx.x;
        const float* W = (n < 64) ? Wv : We;
        int nn = n & 63;
        for (int k = 0; k < 64; k++) {
            float w = W[k * 64 + nn];
            __half h = __float2half_rn(w);
            __half l = __float2half_rn(w - __half2float(h));
            d_Bimg[n * 72 + k]            = h;
            d_Bimg[128 * 72 + n * 72 + k] = l;
        }
    }

    __shared__ float sWq[64 * 64];
    __shared__ float sWk[64 * 65];   // padded stride
    __shared__ float sq[8][64];
    int t = threadIdx.x;
    for (int i = t; i < 1024; i += 256) ((float4*)sWq)[i] = ((const float4*)Wq)[i];
    for (int i = t; i < 4096; i += 256) { int r = i >> 6, c = i & 63; sWk[r * 65 + c] = Wk[i]; }
    __syncthreads();

    int warp = t >> 5, lane = t & 31;
    int n = blockIdx.x * 8 + warp;
    if (n >= Nn) return;

    // q row: lane owns cols 2*lane, 2*lane+1
    float2 x2 = *(const float2*)&x[(size_t)n * 64 + 2 * lane];
    float qa = 0.f, qb = 0.f;
    #pragma unroll
    for (int dd = 0; dd < 32; dd++) {
        float xa = __shfl_sync(0xffffffffu, x2.x, dd);
        float xb = __shfl_sync(0xffffffffu, x2.y, dd);
        float2 w0 = *(const float2*)&sWq[(2 * dd) * 64 + 2 * lane];
        float2 w1 = *(const float2*)&sWq[(2 * dd + 1) * 64 + 2 * lane];
        qa += xa * w0.x + xb * w1.x;
        qb += xa * w0.y + xb * w1.y;
    }
    sq[warp][2 * lane]     = qa;
    sq[warp][2 * lane + 1] = qb;
    __syncwarp();

    // g[n][d][h] = sum_c q[h16+c] * Wk[d, h16+c], fp16, h fastest
    #pragma unroll
    for (int dd = 0; dd < 2; dd++) {
        int d = lane + 32 * dd;
        float gh[4];
        #pragma unroll
        for (int h = 0; h < 4; h++) {
            float acc = 0.f;
            #pragma unroll
            for (int c = 0; c < 16; c++)
                acc += sq[warp][h * 16 + c] * sWk[d * 65 + h * 16 + c];
            gh[h] = acc;
        }
        uint2 gv;
        gv.x = pack_h2(gh[0], gh[1]);
        gv.y = pack_h2(gh[2], gh[3]);
        *(uint2*)&d_g[(size_t)n * 256 + d * 4] = gv;
    }
}

// ================= kernel 3: fused edge pass =================
__global__ void __launch_bounds__(NTHR, 2) edge_kernel(const float* __restrict__ x,
                                                       const void*  __restrict__ eidx,
                                                       const float* __restrict__ ea,
                                                       const float* __restrict__ be,
                                                       float* __restrict__ outp,
                                                       float* __restrict__ eo,
                                                       long long Etot) {
    extern __shared__ __align__(16) char smem[];
    uint32_t smb = smem_u32(smem);
    int t = threadIdx.x, w = t >> 5, l = t & 31;
    int g = l >> 2, t4 = l & 3;

    int*   ssrc = (int*)(smem + SM_SRC);
    float* sbe  = (float*)(smem + SM_BE);
    float* satt = (float*)(smem + SM_ATT);

    long long ebase = (long long)blockIdx.x * EPB;

    // ---- B copy (36864 B contiguous) ----
    {
        const uint4* bs = (const uint4*)d_Bimg;
        uint4* bd = (uint4*)(smem + SM_BHI);
        #pragma unroll
        for (int i = 0; i < 9; i++) bd[t + NTHR * i] = bs[t + NTHR * i];
    }
    if (t < 64) sbe[t] = be[t];

    // ---- A build + score: 8 lanes per edge, coalesced ----
    {
        int oct = t & 7;
        int elb = t >> 3;                     // 0..31
        #pragma unroll
        for (int p = 0; p < 8; p++) {
            int eb = elb + 32 * p;            // edge within block
            long long e = ebase + eb;
            bool valid = (e < Etot);
            int src = 0; long long nbr = 0;
            if (valid) { src = (int)load_idx(eidx, e); nbr = load_idx(eidx, Etot + e); }
            if (oct == 0) ssrc[eb] = src;

            // Z for this lane: cols oct*4..+3 and 32+oct*4..+3
            float zv[8];
            #pragma unroll
            for (int h2 = 0; h2 < 2; h2++) {
                float4 a4, x4;
                if (valid) {
                    a4 = *(const float4*)(ea + (size_t)e * 64 + h2 * 32 + oct * 4);
                    x4 = *(const float4*)(x + (size_t)nbr * 64 + h2 * 32 + oct * 4);
                } else {
                    a4 = make_float4(0.f, 0.f, 0.f, 0.f);
                    x4 = a4;
                }
                zv[h2 * 4 + 0] = a4.x * x4.x; zv[h2 * 4 + 1] = a4.y * x4.y;
                zv[h2 * 4 + 2] = a4.z * x4.z; zv[h2 * 4 + 3] = a4.w * x4.w;
                uint2 hv = make_uint2(pack_h2(zv[h2 * 4 + 0], zv[h2 * 4 + 1]),
                                      pack_h2(zv[h2 * 4 + 2], zv[h2 * 4 + 3]));
                *(uint2*)(smem + SM_AHI + (uint32_t)eb * 144 + h2 * 64 + oct * 8) = hv;
            }

            // g gather: d_g[src] row = 256 halves = 32 uint4.
            // This lane needs d = oct*4..+3 (halves oct*16..+15 = uint4 2*oct, 2*oct+1)
            // and d = 32+oct*4..+3 (uint4 16+2*oct, 16+2*oct+1): 64 bytes total.
            const uint4* gp4 = (const uint4*)(d_g + (size_t)src * 256);
            __half2 gh[16];
            *(uint4*)&gh[0]  = gp4[2 * oct];
            *(uint4*)&gh[4]  = gp4[2 * oct + 1];
            *(uint4*)&gh[8]  = gp4[16 + 2 * oct];
            *(uint4*)&gh[12] = gp4[16 + 2 * oct + 1];

            float acc0 = 0.f, acc1 = 0.f, acc2 = 0.f, acc3 = 0.f;
            #pragma unroll
            for (int i = 0; i < 8; i++) {
                float2 p01 = __half22float2(gh[2 * i]);
                float2 p23 = __half22float2(gh[2 * i + 1]);
                acc0 += zv[i] * p01.x; acc1 += zv[i] * p01.y;
                acc2 += zv[i] * p23.x; acc3 += zv[i] * p23.y;
            }
            // oct butterfly (lanes 8e..8e+7)
            #pragma unroll
            for (int m = 1; m < 8; m <<= 1) {
                acc0 += __shfl_xor_sync(0xffffffffu, acc0, m);
                acc1 += __shfl_xor_sync(0xffffffffu, acc1, m);
                acc2 += __shfl_xor_sync(0xffffffffu, acc2, m);
                acc3 += __shfl_xor_sync(0xffffffffu, acc3, m);
            }
            if (oct == 0) {
                float4 ev = make_float4(__expf(acc0 * 0.25f), __expf(acc1 * 0.25f),
                                        __expf(acc2 * 0.25f), __expf(acc3 * 0.25f));
                *(float4*)&satt[eb * 4] = ev;
                if (valid) red4(&d_denom[(size_t)src * 4], ev);
            }
        }
    }
    __syncthreads();

    // ---------------- per-warp: rows rb .. rb+31 (2 m-tiles) ----------------
    int rb = w * 32;

    int  srow[2][2];
    bool vrow[2][2];
    #pragma unroll
    for (int mt = 0; mt < 2; mt++)
        #pragma unroll
        for (int r = 0; r < 2; r++) {
            int row = rb + mt * 16 + g + 8 * r;
            srow[mt][r] = ssrc[row];
            vrow[mt][r] = (ebase + row) < Etot;
        }

    // ---- A fragments via ldmatrix.x4 ----
    uint32_t afh[2][4][4];
    {
        uint32_t rowsel = (uint32_t)(l & 15);
        uint32_t koff = (uint32_t)(l >> 4) * 16;
        #pragma unroll
        for (int mt = 0; mt < 2; mt++) {
            uint32_t ab = smb + SM_AHI + (rb + mt * 16 + rowsel) * 144 + koff;
            #pragma unroll
            for (int ks = 0; ks < 4; ks++)
                LDMX4(afh[mt][ks], ab + ks * 32);
        }
    }

    // B per-lane base: lanes 0-15 -> hi matrices, 16-31 -> lo matrices
    uint32_t bb4 = smb + ((l < 16) ? SM_BHI : SM_BLO)
                 + (uint32_t)(l & 7) * 144 + (uint32_t)((l >> 3) & 1) * 16;

    // ---- v | eo sweep (cols 0..127), Z_fp16 . (W_hi + W_lo) ----
    bool even = ((t4 & 1) == 0);
    int colb = even ? (2 * t4) : (2 * (t4 - 1));   // 0 or 4
    int r = even ? 0 : 1;

    float a00 = 0.f, a01 = 0.f, a10 = 0.f, a11 = 0.f;

    #pragma unroll
    for (int j = 0; j < 16; j++) {
        if (j < 8 && (j & 1) == 0) {
            int h = j >> 1;
            a00 = satt[(rb + g) * 4 + h];
            a01 = satt[(rb + g + 8) * 4 + h];
            a10 = satt[(rb + 16 + g) * 4 + h];
            a11 = satt[(rb + 16 + g + 8) * 4 + h];
        }

        float c[2][4];
        #pragma unroll
        for (int mt = 0; mt < 2; mt++)
            #pragma unroll
            for (int i = 0; i < 4; i++) c[mt][i] = 0.f;

        #pragma unroll
        for (int ks = 0; ks < 4; ks++) {
            uint32_t bo = (uint32_t)(8 * j) * 144 + ks * 32;
            uint32_t b4[4];
            LDMX4(b4, bb4 + bo);          // {bh0, bh1, bl0, bl1}
            mma16816(c[0], afh[0][ks], b4[0], b4[1]);
            mma16816(c[0], afh[0][ks], b4[2], b4[3]);
            mma16816(c[1], afh[1][ks], b4[0], b4[1]);
            mma16816(c[1], afh[1][ks], b4[2], b4[3]);
        }

        #pragma unroll
        for (int mt = 0; mt < 2; mt++) {
            float v0 = c[mt][0], v1 = c[mt][1], v2 = c[mt][2], v3 = c[mt][3];
            if (j < 8) {
                float s0 = (mt == 0) ? a00 : a10;
                float s1 = (mt == 0) ? a01 : a11;
                v0 *= s0; v1 *= s0; v2 *= s1; v3 *= s1;
            } else {
                int ec = 8 * (j - 8) + 2 * t4;
                float b0 = sbe[ec], b1 = sbe[ec + 1];
                v0 += b0; v1 += b1; v2 += b0; v3 += b1;
            }
            float o0 = __shfl_xor_sync(0xffffffffu, v0, 1);
            float o1 = __shfl_xor_sync(0xffffffffu, v1, 1);
            float o2 = __shfl_xor_sync(0xffffffffu, v2, 1);
            float o3 = __shfl_xor_sync(0xffffffffu, v3, 1);
            float4 vv = even ? make_float4(v0, v1, o0, o1)
                             : make_float4(o2, o3, v2, v3);
            if (vrow[mt][r]) {
                if (j < 8) {
                    red4(outp + (size_t)srow[mt][r] * 64 + 8 * j + colb, vv);
                } else {
                    long long row = ebase + rb + mt * 16 + g + 8 * r;
                    *(float4*)(eo + row * 64 + 8 * (j - 8) + colb) = vv;
                }
            }
        }
    }
}

// ================= kernel 4: normalize =================
__global__ void norm_kernel(float4* __restrict__ out, int Nn) {
    int i = blockIdx.x * blockDim.x + threadIdx.x;
    if (i >= Nn * 16) return;
    int n = i >> 4;
    int h = (i >> 2) & 3;
    float dinv = 1.0f / (d_denom[n * 4 + h] + 1e-16f);
    float4 v = out[i];
    v.x *= dinv; v.y *= dinv; v.z *= dinv; v.w *= dinv;
    out[i] = v;
}

// ================= launch =================
extern "C" void kernel_launch(void* const* d_in, const int* in_sizes, int n_in,
                              void* d_out, int out_size) {
    const float* x   = (const float*)d_in[0];
    const void*  eix = d_in[1];
    const float* ea  = (const float*)d_in[2];
    const float* Wq  = (const float*)d_in[3];
    const float* Wk  = (const float*)d_in[4];
    const float* Wv  = (const float*)d_in[5];
    const float* We  = (const float*)d_in[6];
    const float* be  = (const float*)d_in[7];

    int       Nn   = in_sizes[0] / 64;
    long long Etot = (long long)in_sizes[2] / 64;

    float* outp = (float*)d_out;
    float* eo   = outp + (size_t)Nn * 64;

    static int cfg = 0;
    if (!cfg) {
        cudaFuncSetAttribute(edge_kernel, cudaFuncAttributeMaxDynamicSharedMemorySize, SMEM_BYTES);
        cfg = 1;
    }

    detect_kernel<<<1, 32>>>((const int*)eix);
    zero_kernel<<<2048, 256>>>((float4*)outp, Nn);
    prep_kernel<<<(Nn + 7) / 8, 256>>>(x, Wq, Wv, We, Wk, Nn);
    int eblocks = (int)((Etot + EPB - 1) / EPB);
    edge_kernel<<<eblocks, NTHR, SMEM_BYTES>>>(x, eix, ea, be, outp, eo, Etot);
    norm_kernel<<<(Nn * 16 + 255) / 256, 256>>>((float4*)outp, Nn);
}

// round 13
// speedup vs baseline: 1.0938x; 1.0938x over previous
#include <cuda_runtime.h>
#include <cuda_fp16.h>
#include <cstdint>

#define MAXN 100000
#define EPB  256            // edges per block
#define NTHR 256

// ---------------- device scratch ----------------
__device__ __half d_q[(size_t)MAXN * 64];                // q[n][h*16+c] fp16, 12.8 MB
__device__ float d_denom[MAXN * 4];                      // per (node, head)
__device__ __align__(16) __half d_Bimg[192 * 72];        // fp16 B: cols 0..63 Wv, 64..127 We, 128..191 Wk
__device__ int g_is64;

// ---------------- helpers ----------------
__device__ __forceinline__ void red4(float* p, float4 v) {
    asm volatile("red.global.add.v4.f32 [%0], {%1, %2, %3, %4};"
                 :: "l"(p), "f"(v.x), "f"(v.y), "f"(v.z), "f"(v.w) : "memory");
}
__device__ __forceinline__ long long load_idx(const void* p, long long i) {
    if (g_is64) return ((const long long*)p)[i];
    return (long long)((const int*)p)[i];
}
__device__ __forceinline__ uint32_t smem_u32(const void* p) {
    uint32_t a;
    asm("{ .reg .u64 t; cvta.to.shared.u64 t, %1; cvt.u32.u64 %0, t; }" : "=r"(a) : "l"(p));
    return a;
}
__device__ __forceinline__ uint32_t pack_h2(float a, float b) {
    __half2 h = __floats2half2_rn(a, b);
    return *(uint32_t*)&h;
}
__device__ __forceinline__ void mma16816(float c[4], const uint32_t a[4],
                                         uint32_t b0, uint32_t b1) {
    asm volatile("mma.sync.aligned.m16n8k16.row.col.f32.f16.f16.f32 "
                 "{%0,%1,%2,%3}, {%4,%5,%6,%7}, {%8,%9}, {%0,%1,%2,%3};"
                 : "+f"(c[0]), "+f"(c[1]), "+f"(c[2]), "+f"(c[3])
                 : "r"(a[0]), "r"(a[1]), "r"(a[2]), "r"(a[3]), "r"(b0), "r"(b1));
}
#define LDMX4(r, a)                                                        \
    asm volatile("ldmatrix.sync.aligned.m8n8.x4.shared.b16 {%0,%1,%2,%3}, [%4];" \
        : "=r"((r)[0]), "=r"((r)[1]), "=r"((r)[2]), "=r"((r)[3]) : "r"(a))
#define LDMX2(r, a)                                                        \
    asm volatile("ldmatrix.sync.aligned.m8n8.x2.shared.b16 {%0,%1}, [%2];" \
        : "=r"((r)[0]), "=r"((r)[1]) : "r"(a))

// ---------------- smem layout (bytes) ----------------
#define SM_SRC 0                       // int[256]            1024
#define SM_BE  1024                    // float[64]           256
#define SM_ATT 1280                    // float[256*4]        4096
#define SM_BHI 5376                    // half[192][72]       27648
#define SM_AHI 33024                   // half[256][72]       36864  (Z in fp16)
#define SM_Q   69888                   // half[256], 136B row 34816
#define SMEM_BYTES 104704

// ================= kernel 0: dtype detect =================
__global__ void detect_kernel(const int* __restrict__ p) {
    if (threadIdx.x == 0) {
        int any = 0;
        for (int i = 1; i < 256; i += 2) any |= p[i];
        g_is64 = (any == 0) ? 1 : 0;
    }
}

// ================= kernel 1: zero out + denom =================
__global__ void zero_kernel(float4* __restrict__ out, int Nn) {
    int i = blockIdx.x * blockDim.x + threadIdx.x;
    int st = gridDim.x * blockDim.x;
    float4 z = make_float4(0.f, 0.f, 0.f, 0.f);
    int n4 = Nn * 16;
    for (int j = i; j < n4; j += st) out[j] = z;
    float4* dn = (float4*)d_denom;
    for (int j = i; j < Nn; j += st) dn[j] = z;
}

// ================= kernel 2: q = x @ Wq (fp16)  (+ block 0 builds B image) =================
__global__ void __launch_bounds__(256) prep_kernel(const float* __restrict__ x,
                                                   const float* __restrict__ Wq,
                                                   const float* __restrict__ Wv,
                                                   const float* __restrict__ We,
                                                   const float* __restrict__ Wk,
                                                   int Nn) {
    if (blockIdx.x == 0 && threadIdx.x < 192) {
        int n = threadIdx.x;
        const float* W = (n < 64) ? Wv : ((n < 128) ? We : Wk);
        int nn = n & 63;
        for (int k = 0; k < 64; k++)
            d_Bimg[n * 72 + k] = __float2half_rn(W[k * 64 + nn]);
    }

    __shared__ float sWq[64 * 64];
    int t = threadIdx.x;
    for (int i = t; i < 1024; i += 256) ((float4*)sWq)[i] = ((const float4*)Wq)[i];
    __syncthreads();

    int warp = t >> 5, lane = t & 31;
    int n = blockIdx.x * 8 + warp;
    if (n >= Nn) return;

    float2 x2 = *(const float2*)&x[(size_t)n * 64 + 2 * lane];
    float qa = 0.f, qb = 0.f;
    #pragma unroll
    for (int dd = 0; dd < 32; dd++) {
        float xa = __shfl_sync(0xffffffffu, x2.x, dd);
        float xb = __shfl_sync(0xffffffffu, x2.y, dd);
        float2 w0 = *(const float2*)&sWq[(2 * dd) * 64 + 2 * lane];
        float2 w1 = *(const float2*)&sWq[(2 * dd + 1) * 64 + 2 * lane];
        qa += xa * w0.x + xb * w1.x;
        qb += xa * w0.y + xb * w1.y;
    }
    ((uint32_t*)d_q)[(size_t)n * 32 + lane] = pack_h2(qa, qb);
}

// ================= kernel 3: fused edge pass =================
__global__ void __launch_bounds__(NTHR, 2) edge_kernel(const float* __restrict__ x,
                                                       const void*  __restrict__ eidx,
                                                       const float* __restrict__ ea,
                                                       const float* __restrict__ be,
                                                       float* __restrict__ outp,
                                                       float* __restrict__ eo,
                                                       long long Etot) {
    extern __shared__ __align__(16) char smem[];
    uint32_t smb = smem_u32(smem);
    int t = threadIdx.x, w = t >> 5, l = t & 31;
    int g = l >> 2, t4 = l & 3;

    int*   ssrc = (int*)(smem + SM_SRC);
    float* sbe  = (float*)(smem + SM_BE);
    float* satt = (float*)(smem + SM_ATT);

    long long ebase = (long long)blockIdx.x * EPB;

    // ---- B copy (27648 B = 1728 uint4) ----
    {
        const uint4* bs = (const uint4*)d_Bimg;
        uint4* bd = (uint4*)(smem + SM_BHI);
        #pragma unroll
        for (int i = 0; i < 7; i++) {
            int idx = t + NTHR * i;
            if (idx < 1728) bd[idx] = bs[idx];
        }
    }
    if (t < 64) sbe[t] = be[t];

    // ---- A build: 8 lanes per edge, coalesced. Z = ea * x[nbr] fp16; q row -> smem ----
    {
        int oct = t & 7;
        int elb = t >> 3;                     // 0..31
        #pragma unroll
        for (int p = 0; p < 8; p++) {
            int eb = elb + 32 * p;            // edge within block
            long long e = ebase + eb;
            bool valid = (e < Etot);
            int src = 0; long long nbr = 0;
            if (valid) { src = (int)load_idx(eidx, e); nbr = load_idx(eidx, Etot + e); }
            if (oct == 0) ssrc[eb] = src;
            #pragma unroll
            for (int h2 = 0; h2 < 2; h2++) {
                float4 a4, x4;
                if (valid) {
                    a4 = *(const float4*)(ea + (size_t)e * 64 + h2 * 32 + oct * 4);
                    x4 = *(const float4*)(x + (size_t)nbr * 64 + h2 * 32 + oct * 4);
                } else {
                    a4 = make_float4(0.f, 0.f, 0.f, 0.f);
                    x4 = a4;
                }
                uint2 hv = make_uint2(pack_h2(a4.x * x4.x, a4.y * x4.y),
                                      pack_h2(a4.z * x4.z, a4.w * x4.w));
                *(uint2*)(smem + SM_AHI + (uint32_t)eb * 144 + h2 * 64 + oct * 8) = hv;
            }
            // q gather: row = 128 B = 8 uint4; lane oct takes 16 B (1 wavefront/edge)
            uint4 qv = ((const uint4*)(d_q + (size_t)src * 64))[oct];
            char* qs = smem + SM_Q + (uint32_t)eb * 136 + oct * 16;
            *(uint2*)qs       = make_uint2(qv.x, qv.y);
            *(uint2*)(qs + 8) = make_uint2(qv.z, qv.w);
        }
    }
    __syncthreads();

    // ---------------- per-warp: rows rb .. rb+31 (2 m-tiles) ----------------
    int rb = w * 32;

    int  srow[2][2];
    bool vrow[2][2];
    #pragma unroll
    for (int mt = 0; mt < 2; mt++)
        #pragma unroll
        for (int r = 0; r < 2; r++) {
            int row = rb + mt * 16 + g + 8 * r;
            srow[mt][r] = ssrc[row];
            vrow[mt][r] = (ebase + row) < Etot;
        }

    // ---- A fragments via ldmatrix.x4 ----
    uint32_t afh[2][4][4];
    {
        uint32_t rowsel = (uint32_t)(l & 15);
        uint32_t koff = (uint32_t)(l >> 4) * 16;
        #pragma unroll
        for (int mt = 0; mt < 2; mt++) {
            uint32_t ab = smb + SM_AHI + (rb + mt * 16 + rowsel) * 144 + koff;
            #pragma unroll
            for (int ks = 0; ks < 4; ks++)
                LDMX4(afh[mt][ks], ab + ks * 32);
        }
    }

    // B per-lane base (lanes 0-15 meaningful for x2)
    uint32_t bb = smb + SM_BHI + (uint32_t)(l & 7) * 144 + (uint32_t)((l >> 3) & 1) * 16;

    // q smem rows for this lane
    const char* sq0 = smem + SM_Q + (rb + g) * 136;
    const char* sq1 = smem + SM_Q + (rb + g + 8) * 136;
    const char* sq2 = smem + SM_Q + (rb + 16 + g) * 136;
    const char* sq3 = smem + SM_Q + (rb + 24 + g) * 136;

    // ---- k path (B cols 128..191) ----
    {
        float ps[2][2][4];
        #pragma unroll
        for (int mt = 0; mt < 2; mt++)
            #pragma unroll
            for (int r = 0; r < 2; r++)
                #pragma unroll
                for (int h = 0; h < 4; h++) ps[mt][r][h] = 0.f;

        #pragma unroll
        for (int j = 0; j < 8; j++) {
            float c0[4] = {0.f, 0.f, 0.f, 0.f};
            float c1[4] = {0.f, 0.f, 0.f, 0.f};
            #pragma unroll
            for (int ks = 0; ks < 4; ks++) {
                uint32_t bo = (uint32_t)(128 + 8 * j) * 144 + ks * 32;
                uint32_t bh[2];
                LDMX2(bh, bb + bo);
                mma16816(c0, afh[0][ks], bh[0], bh[1]);
                mma16816(c1, afh[1][ks], bh[0], bh[1]);
            }
            int qoff = 16 * j + 4 * t4;
            float2 qa = __half22float2(*(const __half2*)(sq0 + qoff));
            float2 qb = __half22float2(*(const __half2*)(sq1 + qoff));
            float2 qc = __half22float2(*(const __half2*)(sq2 + qoff));
            float2 qd = __half22float2(*(const __half2*)(sq3 + qoff));
            int h = j >> 1;
            ps[0][0][h] += c0[0] * qa.x + c0[1] * qa.y;
            ps[0][1][h] += c0[2] * qb.x + c0[3] * qb.y;
            ps[1][0][h] += c1[0] * qc.x + c1[1] * qc.y;
            ps[1][1][h] += c1[2] * qd.x + c1[3] * qd.y;
        }

        // quad-reduce + exp -> satt; denom scatter
        #pragma unroll
        for (int mt = 0; mt < 2; mt++)
            #pragma unroll
            for (int r = 0; r < 2; r++) {
                float v0 = ps[mt][r][0], v1 = ps[mt][r][1];
                float v2 = ps[mt][r][2], v3 = ps[mt][r][3];
                v0 += __shfl_xor_sync(0xffffffffu, v0, 1);
                v1 += __shfl_xor_sync(0xffffffffu, v1, 1);
                v2 += __shfl_xor_sync(0xffffffffu, v2, 1);
                v3 += __shfl_xor_sync(0xffffffffu, v3, 1);
                v0 += __shfl_xor_sync(0xffffffffu, v0, 2);
                v1 += __shfl_xor_sync(0xffffffffu, v1, 2);
                v2 += __shfl_xor_sync(0xffffffffu, v2, 2);
                v3 += __shfl_xor_sync(0xffffffffu, v3, 2);
                float a0 = __expf(v0 * 0.25f), a1 = __expf(v1 * 0.25f);
                float a2 = __expf(v2 * 0.25f), a3 = __expf(v3 * 0.25f);
                int row = rb + mt * 16 + g + 8 * r;
                if (t4 == 0)
                    *(float4*)&satt[row * 4] = make_float4(a0, a1, a2, a3);
                if (t4 == 1 && vrow[mt][r])
                    red4(&d_denom[(size_t)srow[mt][r] * 4], make_float4(a0, a1, a2, a3));
            }
    }
    __syncwarp();

    // ---- v | eo sweep (cols 0..127), Z_fp16 . W_fp16 ----
    bool even = ((t4 & 1) == 0);
    int colb = even ? (2 * t4) : (2 * (t4 - 1));   // 0 or 4
    int r = even ? 0 : 1;

    float a00 = 0.f, a01 = 0.f, a10 = 0.f, a11 = 0.f;

    #pragma unroll
    for (int j = 0; j < 16; j++) {
        if (j < 8 && (j & 1) == 0) {
            int h = j >> 1;
            a00 = satt[(rb + g) * 4 + h];
            a01 = satt[(rb + g + 8) * 4 + h];
            a10 = satt[(rb + 16 + g) * 4 + h];
            a11 = satt[(rb + 16 + g + 8) * 4 + h];
        }

        float c[2][4];
        #pragma unroll
        for (int mt = 0; mt < 2; mt++)
            #pragma unroll
            for (int i = 0; i < 4; i++) c[mt][i] = 0.f;

        #pragma unroll
        for (int ks = 0; ks < 4; ks++) {
            uint32_t bo = (uint32_t)(8 * j) * 144 + ks * 32;
            uint32_t bh[2];
            LDMX2(bh, bb + bo);
            mma16816(c[0], afh[0][ks], bh[0], bh[1]);
            mma16816(c[1], afh[1][ks], bh[0], bh[1]);
        }

        #pragma unroll
        for (int mt = 0; mt < 2; mt++) {
            float v0 = c[mt][0], v1 = c[mt][1], v2 = c[mt][2], v3 = c[mt][3];
            if (j < 8) {
                float s0 = (mt == 0) ? a00 : a10;
                float s1 = (mt == 0) ? a01 : a11;
                v0 *= s0; v1 *= s0; v2 *= s1; v3 *= s1;
            } else {
                int ec = 8 * (j - 8) + 2 * t4;
                float b0 = sbe[ec], b1 = sbe[ec + 1];
                v0 += b0; v1 += b1; v2 += b0; v3 += b1;
            }
            float o0 = __shfl_xor_sync(0xffffffffu, v0, 1);
            float o1 = __shfl_xor_sync(0xffffffffu, v1, 1);
            float o2 = __shfl_xor_sync(0xffffffffu, v2, 1);
            float o3 = __shfl_xor_sync(0xffffffffu, v3, 1);
            float4 vv = even ? make_float4(v0, v1, o0, o1)
                             : make_float4(o2, o3, v2, v3);
            if (vrow[mt][r]) {
                if (j < 8) {
                    red4(outp + (size_t)srow[mt][r] * 64 + 8 * j + colb, vv);
                } else {
                    long long row = ebase + rb + mt * 16 + g + 8 * r;
                    *(float4*)(eo + row * 64 + 8 * (j - 8) + colb) = vv;
                }
            }
        }
    }
}

// ================= kernel 4: normalize =================
__global__ void norm_kernel(float4* __restrict__ out, int Nn) {
    int i = blockIdx.x * blockDim.x + threadIdx.x;
    if (i >= Nn * 16) return;
    int n = i >> 4;
    int h = (i >> 2) & 3;
    float dinv = 1.0f / (d_denom[n * 4 + h] + 1e-16f);
    float4 v = out[i];
    v.x *= dinv; v.y *= dinv; v.z *= dinv; v.w *= dinv;
    out[i] = v;
}

// ================= launch =================
extern "C" void kernel_launch(void* const* d_in, const int* in_sizes, int n_in,
                              void* d_out, int out_size) {
    const float* x   = (const float*)d_in[0];
    const void*  eix = d_in[1];
    const float* ea  = (const float*)d_in[2];
    const float* Wq  = (const float*)d_in[3];
    const float* Wk  = (const float*)d_in[4];
    const float* Wv  = (const float*)d_in[5];
    const float* We  = (const float*)d_in[6];
    const float* be  = (const float*)d_in[7];

    int       Nn   = in_sizes[0] / 64;
    long long Etot = (long long)in_sizes[2] / 64;

    float* outp = (float*)d_out;
    float* eo   = outp + (size_t)Nn * 64;

    static int cfg = 0;
    if (!cfg) {
        cudaFuncSetAttribute(edge_kernel, cudaFuncAttributeMaxDynamicSharedMemorySize, SMEM_BYTES);
        cfg = 1;
    }

    detect_kernel<<<1, 32>>>((const int*)eix);
    zero_kernel<<<2048, 256>>>((float4*)outp, Nn);
    prep_kernel<<<(Nn + 7) / 8, 256>>>(x, Wq, Wv, We, Wk, Nn);
    int eblocks = (int)((Etot + EPB - 1) / EPB);
    edge_kernel<<<eblocks, NTHR, SMEM_BYTES>>>(x, eix, ea, be, outp, eo, Etot);
    norm_kernel<<<(Nn * 16 + 255) / 256, 256>>>((float4*)outp, Nn);
}

// round 14
// speedup vs baseline: 1.2181x; 1.1137x over previous
#include <cuda_runtime.h>
#include <cuda_fp16.h>
#include <cstdint>

#define MAXN 100000
#define EPB  256            // edges per block
#define NTHR 256

// ---------------- device scratch ----------------
__device__ __half d_q[(size_t)MAXN * 64];                // q[n][h*16+c] fp16, 12.8 MB
__device__ float d_denom[MAXN * 4];                      // per (node, head)
__device__ __align__(16) __half d_Bimg[2 * 192 * 72];    // [hi(192 cols) | lo(192 cols)][k pad 72]
__device__ int g_is64;

// ---------------- helpers ----------------
__device__ __forceinline__ void red4(float* p, float4 v) {
    asm volatile("red.global.add.v4.f32 [%0], {%1, %2, %3, %4};"
                 :: "l"(p), "f"(v.x), "f"(v.y), "f"(v.z), "f"(v.w) : "memory");
}
__device__ __forceinline__ long long load_idx(const void* p, long long i) {
    if (g_is64) return ((const long long*)p)[i];
    return (long long)((const int*)p)[i];
}
__device__ __forceinline__ uint32_t smem_u32(const void* p) {
    uint32_t a;
    asm("{ .reg .u64 t; cvta.to.shared.u64 t, %1; cvt.u32.u64 %0, t; }" : "=r"(a) : "l"(p));
    return a;
}
__device__ __forceinline__ uint32_t pack_h2(float a, float b) {
    __half2 h = __floats2half2_rn(a, b);
    return *(uint32_t*)&h;
}
__device__ __forceinline__ void mma16816(float c[4], const uint32_t a[4],
                                         uint32_t b0, uint32_t b1) {
    asm volatile("mma.sync.aligned.m16n8k16.row.col.f32.f16.f16.f32 "
                 "{%0,%1,%2,%3}, {%4,%5,%6,%7}, {%8,%9}, {%0,%1,%2,%3};"
                 : "+f"(c[0]), "+f"(c[1]), "+f"(c[2]), "+f"(c[3])
                 : "r"(a[0]), "r"(a[1]), "r"(a[2]), "r"(a[3]), "r"(b0), "r"(b1));
}
#define LDMX4(r, a)                                                        \
    asm volatile("ldmatrix.sync.aligned.m8n8.x4.shared.b16 {%0,%1,%2,%3}, [%4];" \
        : "=r"((r)[0]), "=r"((r)[1]), "=r"((r)[2]), "=r"((r)[3]) : "r"(a))
#define LDMX2(r, a)                                                        \
    asm volatile("ldmatrix.sync.aligned.m8n8.x2.shared.b16 {%0,%1}, [%2];" \
        : "=r"((r)[0]), "=r"((r)[1]) : "r"(a))

// ---------------- smem layout (bytes) — identical to R10 ----------------
#define SM_SRC 0                       // int[256]            1024
#define SM_BE  1024                    // float[64]           256
#define SM_ATT 1280                    // float[256*4]        4096
#define SM_BHI 5376                    // half[192][72]       27648  (cols 0..191, hi)
#define SM_BLO 33024                   // half[128][72]       18432  (cols 0..127, lo)
#define SM_AHI 51456                   // half[256][72]       36864  (Z in plain fp16)
#define SMEM_BYTES 88320

// ================= kernel 1: fused setup (detect + zero + B image + q) =================
__global__ void __launch_bounds__(256) setup_kernel(const float* __restrict__ x,
                                                    const int*   __restrict__ eix32,
                                                    const float* __restrict__ Wq,
                                                    const float* __restrict__ Wv,
                                                    const float* __restrict__ We,
                                                    const float* __restrict__ Wk,
                                                    float4* __restrict__ out,
                                                    int Nn) {
    int t = threadIdx.x;

    // block 0: dtype detect + fp16 hi/lo split B image (cols 0..63 Wv, 64..127 We, 128..191 Wk)
    if (blockIdx.x == 0) {
        if (t == 0) {
            int any = 0;
            for (int i = 1; i < 256; i += 2) any |= eix32[i];
            g_is64 = (any == 0) ? 1 : 0;
        }
        if (t < 192) {
            int n = t;
            const float* W = (n < 64) ? Wv : ((n < 128) ? We : Wk);
            int nn = n & 63;
            for (int k = 0; k < 64; k++) {
                float w = W[k * 64 + nn];
                __half h = __float2half_rn(w);
                __half l = __float2half_rn(w - __half2float(h));
                d_Bimg[n * 72 + k]            = h;
                d_Bimg[192 * 72 + n * 72 + k] = l;
            }
        }
    }

    // zero out-accumulator + denom (grid-stride)
    {
        int i = blockIdx.x * blockDim.x + t;
        int st = gridDim.x * blockDim.x;
        float4 z = make_float4(0.f, 0.f, 0.f, 0.f);
        int n4 = Nn * 16;
        for (int j = i; j < n4; j += st) out[j] = z;
        float4* dn = (float4*)d_denom;
        for (int j = i; j < Nn; j += st) dn[j] = z;
    }

    // q = x @ Wq (fp16), grid-stride over node groups; Wq loaded ONCE per block
    __shared__ float sWq[64 * 64];
    for (int i = t; i < 1024; i += 256) ((float4*)sWq)[i] = ((const float4*)Wq)[i];
    __syncthreads();

    int warp = t >> 5, lane = t & 31;
    for (int n0 = blockIdx.x * 8; n0 < Nn; n0 += gridDim.x * 8) {
        int n = n0 + warp;
        if (n >= Nn) continue;
        float2 x2 = *(const float2*)&x[(size_t)n * 64 + 2 * lane];
        float qa = 0.f, qb = 0.f;
        #pragma unroll
        for (int dd = 0; dd < 32; dd++) {
            float xa = __shfl_sync(0xffffffffu, x2.x, dd);
            float xb = __shfl_sync(0xffffffffu, x2.y, dd);
            float2 w0 = *(const float2*)&sWq[(2 * dd) * 64 + 2 * lane];
            float2 w1 = *(const float2*)&sWq[(2 * dd + 1) * 64 + 2 * lane];
            qa += xa * w0.x + xb * w1.x;
            qb += xa * w0.y + xb * w1.y;
        }
        ((uint32_t*)d_q)[(size_t)n * 32 + lane] = pack_h2(qa, qb);
    }
}

// ================= kernel 2: fused edge pass (R10 structure) =================
__global__ void __launch_bounds__(NTHR, 2) edge_kernel(const float* __restrict__ x,
                                                       const void*  __restrict__ eidx,
                                                       const float* __restrict__ ea,
                                                       const float* __restrict__ be,
                                                       float* __restrict__ outp,
                                                       float* __restrict__ eo,
                                                       long long Etot) {
    extern __shared__ __align__(16) char smem[];
    uint32_t smb = smem_u32(smem);
    int t = threadIdx.x, w = t >> 5, l = t & 31;
    int g = l >> 2, t4 = l & 3;

    int*   ssrc = (int*)(smem + SM_SRC);
    float* sbe  = (float*)(smem + SM_BE);
    float* satt = (float*)(smem + SM_ATT);

    long long ebase = (long long)blockIdx.x * EPB;

    // ---- B copy: contiguous prefix of d_Bimg = hi(1728 uint4) + lo cols 0..127 (1152 uint4) ----
    {
        const uint4* bs = (const uint4*)d_Bimg;
        uint4* bd = (uint4*)(smem + SM_BHI);
        #pragma unroll
        for (int i = 0; i < 12; i++) {
            int idx = t + NTHR * i;
            if (idx < 2880) bd[idx] = bs[idx];
        }
    }
    if (t < 64) sbe[t] = be[t];

    // ---- A build: 8 lanes per edge, coalesced. Z = ea * x[nbr] in plain fp16 ----
    {
        int oct = t & 7;
        int elb = t >> 3;                     // 0..31
        #pragma unroll
        for (int p = 0; p < 8; p++) {
            int eb = elb + 32 * p;            // edge within block
            long long e = ebase + eb;
            bool valid = (e < Etot);
            int src = 0; long long nbr = 0;
            if (valid) { src = (int)load_idx(eidx, e); nbr = load_idx(eidx, Etot + e); }
            if (oct == 0) ssrc[eb] = src;
            #pragma unroll
            for (int h2 = 0; h2 < 2; h2++) {
                float4 a4, x4;
                if (valid) {
                    a4 = *(const float4*)(ea + (size_t)e * 64 + h2 * 32 + oct * 4);
                    x4 = *(const float4*)(x + (size_t)nbr * 64 + h2 * 32 + oct * 4);
                } else {
                    a4 = make_float4(0.f, 0.f, 0.f, 0.f);
                    x4 = a4;
                }
                uint2 hv = make_uint2(pack_h2(a4.x * x4.x, a4.y * x4.y),
                                      pack_h2(a4.z * x4.z, a4.w * x4.w));
                *(uint2*)(smem + SM_AHI + (uint32_t)eb * 144 + h2 * 64 + oct * 8) = hv;
            }
        }
    }
    __syncthreads();

    // ---------------- per-warp: rows rb .. rb+31 (2 m-tiles) ----------------
    int rb = w * 32;

    int  srow[2][2];
    bool vrow[2][2];
    #pragma unroll
    for (int mt = 0; mt < 2; mt++)
        #pragma unroll
        for (int r = 0; r < 2; r++) {
            int row = rb + mt * 16 + g + 8 * r;
            srow[mt][r] = ssrc[row];
            vrow[mt][r] = (ebase + row) < Etot;
        }

    // ---- A fragments via ldmatrix.x4 (hi only) ----
    uint32_t afh[2][4][4];
    {
        uint32_t rowsel = (uint32_t)(l & 15);
        uint32_t koff = (uint32_t)(l >> 4) * 16;
        #pragma unroll
        for (int mt = 0; mt < 2; mt++) {
            uint32_t ab = smb + SM_AHI + (rb + mt * 16 + rowsel) * 144 + koff;
            #pragma unroll
            for (int ks = 0; ks < 4; ks++)
                LDMX4(afh[mt][ks], ab + ks * 32);
        }
    }

    // B per-lane bases (lanes 0-15 meaningful for x2)
    uint32_t lane_off = (uint32_t)(l & 7) * 144 + (uint32_t)((l >> 3) & 1) * 16;
    uint32_t bbh = smb + SM_BHI + lane_off;
    uint32_t bbl = smb + SM_BLO + lane_off;

    // ---- k path (B_hi cols 128..191), Z_fp16 . W_hi ----
    {
        const __half* q00 = d_q + (size_t)srow[0][0] * 64;
        const __half* q01 = d_q + (size_t)srow[0][1] * 64;
        const __half* q10 = d_q + (size_t)srow[1][0] * 64;
        const __half* q11 = d_q + (size_t)srow[1][1] * 64;

        float ps[2][2][4];
        #pragma unroll
        for (int mt = 0; mt < 2; mt++)
            #pragma unroll
            for (int r = 0; r < 2; r++)
                #pragma unroll
                for (int h = 0; h < 4; h++) ps[mt][r][h] = 0.f;

        #pragma unroll
        for (int j = 0; j < 8; j++) {
            float c0[4] = {0.f, 0.f, 0.f, 0.f};
            float c1[4] = {0.f, 0.f, 0.f, 0.f};
            #pragma unroll
            for (int ks = 0; ks < 4; ks++) {
                uint32_t bo = (uint32_t)(128 + 8 * j) * 144 + ks * 32;
                uint32_t bh[2];
                LDMX2(bh, bbh + bo);
                mma16816(c0, afh[0][ks], bh[0], bh[1]);
                mma16816(c1, afh[1][ks], bh[0], bh[1]);
            }
            int jc = 8 * j + 2 * t4;
            float2 qa = __half22float2(*(const __half2*)(q00 + jc));
            float2 qb = __half22float2(*(const __half2*)(q01 + jc));
            float2 qc = __half22float2(*(const __half2*)(q10 + jc));
            float2 qd = __half22float2(*(const __half2*)(q11 + jc));
            int h = j >> 1;
            ps[0][0][h] += c0[0] * qa.x + c0[1] * qa.y;
            ps[0][1][h] += c0[2] * qb.x + c0[3] * qb.y;
            ps[1][0][h] += c1[0] * qc.x + c1[1] * qc.y;
            ps[1][1][h] += c1[2] * qd.x + c1[3] * qd.y;
        }

        // quad-reduce + exp -> satt; denom scatter
        #pragma unroll
        for (int mt = 0; mt < 2; mt++)
            #pragma unroll
            for (int r = 0; r < 2; r++) {
                float v0 = ps[mt][r][0], v1 = ps[mt][r][1];
                float v2 = ps[mt][r][2], v3 = ps[mt][r][3];
                v0 += __shfl_xor_sync(0xffffffffu, v0, 1);
                v1 += __shfl_xor_sync(0xffffffffu, v1, 1);
                v2 += __shfl_xor_sync(0xffffffffu, v2, 1);
                v3 += __shfl_xor_sync(0xffffffffu, v3, 1);
                v0 += __shfl_xor_sync(0xffffffffu, v0, 2);
                v1 += __shfl_xor_sync(0xffffffffu, v1, 2);
                v2 += __shfl_xor_sync(0xffffffffu, v2, 2);
                v3 += __shfl_xor_sync(0xffffffffu, v3, 2);
                float a0 = __expf(v0 * 0.25f), a1 = __expf(v1 * 0.25f);
                float a2 = __expf(v2 * 0.25f), a3 = __expf(v3 * 0.25f);
                int row = rb + mt * 16 + g + 8 * r;
                if (t4 == 0)
                    *(float4*)&satt[row * 4] = make_float4(a0, a1, a2, a3);
                if (t4 == 1 && vrow[mt][r])
                    red4(&d_denom[(size_t)srow[mt][r] * 4], make_float4(a0, a1, a2, a3));
            }
    }
    __syncwarp();

    // ---- v | eo sweep (cols 0..127), Z_fp16 . (W_hi + W_lo), B shared across m-tiles ----
    bool even = ((t4 & 1) == 0);
    int colb = even ? (2 * t4) : (2 * (t4 - 1));   // 0 or 4
    int r = even ? 0 : 1;

    float a00 = 0.f, a01 = 0.f, a10 = 0.f, a11 = 0.f;

    #pragma unroll
    for (int j = 0; j < 16; j++) {
        if (j < 8 && (j & 1) == 0) {
            int h = j >> 1;
            a00 = satt[(rb + g) * 4 + h];
            a01 = satt[(rb + g + 8) * 4 + h];
            a10 = satt[(rb + 16 + g) * 4 + h];
            a11 = satt[(rb + 16 + g + 8) * 4 + h];
        }

        float c[2][4];
        #pragma unroll
        for (int mt = 0; mt < 2; mt++)
            #pragma unroll
            for (int i = 0; i < 4; i++) c[mt][i] = 0.f;

        #pragma unroll
        for (int ks = 0; ks < 4; ks++) {
            uint32_t bo = (uint32_t)(8 * j) * 144 + ks * 32;
            uint32_t bh[2], bl[2];
            LDMX2(bh, bbh + bo);
            LDMX2(bl, bbl + bo);
            mma16816(c[0], afh[0][ks], bh[0], bh[1]);
            mma16816(c[0], afh[0][ks], bl[0], bl[1]);
            mma16816(c[1], afh[1][ks], bh[0], bh[1]);
            mma16816(c[1], afh[1][ks], bl[0], bl[1]);
        }

        #pragma unroll
        for (int mt = 0; mt < 2; mt++) {
            float v0 = c[mt][0], v1 = c[mt][1], v2 = c[mt][2], v3 = c[mt][3];
            if (j < 8) {
                float s0 = (mt == 0) ? a00 : a10;
                float s1 = (mt == 0) ? a01 : a11;
                v0 *= s0; v1 *= s0; v2 *= s1; v3 *= s1;
            } else {
                int ec = 8 * (j - 8) + 2 * t4;
                float b0 = sbe[ec], b1 = sbe[ec + 1];
                v0 += b0; v1 += b1; v2 += b0; v3 += b1;
            }
            float o0 = __shfl_xor_sync(0xffffffffu, v0, 1);
            float o1 = __shfl_xor_sync(0xffffffffu, v1, 1);
            float o2 = __shfl_xor_sync(0xffffffffu, v2, 1);
            float o3 = __shfl_xor_sync(0xffffffffu, v3, 1);
            float4 vv = even ? make_float4(v0, v1, o0, o1)
                             : make_float4(o2, o3, v2, v3);
            if (vrow[mt][r]) {
                if (j < 8) {
                    red4(outp + (size_t)srow[mt][r] * 64 + 8 * j + colb, vv);
                } else {
                    long long row = ebase + rb + mt * 16 + g + 8 * r;
                    *(float4*)(eo + row * 64 + 8 * (j - 8) + colb) = vv;
                }
            }
        }
    }
}

// ================= kernel 3: normalize =================
__global__ void norm_kernel(float4* __restrict__ out, int Nn) {
    int i = blockIdx.x * blockDim.x + threadIdx.x;
    if (i >= Nn * 16) return;
    int n = i >> 4;
    int h = (i >> 2) & 3;
    float dinv = 1.0f / (d_denom[n * 4 + h] + 1e-16f);
    float4 v = out[i];
    v.x *= dinv; v.y *= dinv; v.z *= dinv; v.w *= dinv;
    out[i] = v;
}

// ================= launch =================
extern "C" void kernel_launch(void* const* d_in, const int* in_sizes, int n_in,
                              void* d_out, int out_size) {
    const float* x   = (const float*)d_in[0];
    const void*  eix = d_in[1];
    const float* ea  = (const float*)d_in[2];
    const float* Wq  = (const float*)d_in[3];
    const float* Wk  = (const float*)d_in[4];
    const float* Wv  = (const float*)d_in[5];
    const float* We  = (const float*)d_in[6];
    const float* be  = (const float*)d_in[7];

    int       Nn   = in_sizes[0] / 64;
    long long Etot = (long long)in_sizes[2] / 64;

    float* outp = (float*)d_out;
    float* eo   = outp + (size_t)Nn * 64;

    static int cfg = 0;
    if (!cfg) {
        cudaFuncSetAttribute(edge_kernel, cudaFuncAttributeMaxDynamicSharedMemorySize, SMEM_BYTES);
        cfg = 1;
    }

    setup_kernel<<<1184, 256>>>(x, (const int*)eix, Wq, Wv, We, Wk, (float4*)outp, Nn);
    int eblocks = (int)((Etot + EPB - 1) / EPB);
    edge_kernel<<<eblocks, NTHR, SMEM_BYTES>>>(x, eix, ea, be, outp, eo, Etot);
    norm_kernel<<<(Nn * 16 + 255) / 256, 256>>>((float4*)outp, Nn);
}